// round 15
// baseline (speedup 1.0000x reference)
#include <cuda_runtime.h>
#include <cuda_bf16.h>
#include <cstdint>

#define NW 10
#define DIM 1024
#define HID 64

// WPH: bf16 w_hi in HMMA k16 B-fragment layout (validated R3-R14), +8 pad tiles.
__device__ __align__(16) unsigned short WPH[131072 + 4096];
// WQ8: s8 fragments for the merged correction, m16n8k32 B layout
// (layout machinery validated numerically in R14). kk<64 half: w*127 ;
// kk>=64 half: w_lo*2^15.
__device__ __align__(16) signed char WQ8[(256 + 8) * 64 * 16];

// ---------------------------------------------------------------------------
// Circuit kernel (R11 reductions): fused RXRY, CNOT ring as one gather,
// RY1 dropped on qubits 0-2 (summed-out bits; output invariant).
// ---------------------------------------------------------------------------
__device__ __forceinline__ void gate1q(float2* psi, int tid, int bit,
    float g00x, float g00y, float g01x, float g01y,
    float g10x, float g10y, float g11x, float g11y)
{
    const int lowmask = bit - 1;
    const int i0 = ((tid & ~lowmask) << 1) | (tid & lowmask);
    const int i1 = i0 | bit;
    const float2 a = psi[i0], b = psi[i1];
    float2 n0, n1;
    n0.x = g00x*a.x - g00y*a.y + g01x*b.x - g01y*b.y;
    n0.y = g00x*a.y + g00y*a.x + g01x*b.y + g01y*b.x;
    n1.x = g10x*a.x - g10y*a.y + g11x*b.x - g11y*b.y;
    n1.y = g10x*a.y + g10y*a.x + g11x*b.y + g11y*b.x;
    psi[i0] = n0; psi[i1] = n1;
}

__device__ __forceinline__ signed char to_s8(float v) {
    int r = __float2int_rn(v);
    r = r > 127 ? 127 : (r < -127 ? -127 : r);
    return (signed char)r;
}

__global__ void qsa_circuit(const float* __restrict__ rx0,
                            const float* __restrict__ ry0,
                            const float* __restrict__ ry1)
{
    __shared__ float2 psi[DIM];
    const int tid = threadIdx.x;   // 512
    const int c = blockIdx.x;      // 0..63

    psi[tid]       = make_float2(0.f, 0.f);
    psi[tid + 512] = make_float2(0.f, 0.f);
    __syncthreads();
    if (tid == 0) psi[c] = make_float2(1.f, 0.f);
    __syncthreads();

    for (int j = 0; j < NW; j++) {
        const int bit = 1 << (NW - 1 - j);
        float s1, c1, s2, c2;
        sincosf(0.5f * rx0[j], &s1, &c1);
        sincosf(0.5f * ry0[j], &s2, &c2);
        gate1q(psi, tid, bit,
               c2*c1,  s2*s1,  -s2*c1, -c2*s1,
               s2*c1, -c2*s1,   c2*c1, -s2*s1);
        __syncthreads();
    }
    {   // CNOT ring: one permutation gather
        float2 v[2];
        #pragma unroll
        for (int rep = 0; rep < 2; rep++) {
            int src = tid + rep * 512;
            #pragma unroll
            for (int j = NW - 1; j >= 0; j--) {
                const int cbit = 1 << (NW - 1 - j);
                const int tbit = 1 << (NW - 1 - ((j + 1) % NW));
                if (src & cbit) src ^= tbit;
            }
            v[rep] = psi[src];
        }
        __syncthreads();
        psi[tid]       = v[0];
        psi[tid + 512] = v[1];
        __syncthreads();
    }
    for (int j = 3; j < NW; j++) {
        const int bit = 1 << (NW - 1 - j);
        float s, cc;
        sincosf(0.5f * ry1[j], &s, &cc);
        gate1q(psi, tid, bit, cc, 0.f, -s, 0.f, s, 0.f, cc, 0.f);
        __syncthreads();
    }

    // scatter column c: bf16 hi into WPH, s8 w*127 / w_lo*2^15 into WQ8
    const int chunk = c >> 4;
    const int s16 = (c >> 3) & 1;
    const int lq  = (c & 7) >> 1;
    const int h   = c & 1;
    const int lane4 = ((c >> 2) & 3);
    const int breg  = (c >> 4) & 1;
    const int jh = c >> 5;          // s8 MMA index for the w half (kk<64)
    const int jl = 2 + (c >> 5);    // s8 MMA index for the w_lo half (kk>=64)
    #pragma unroll
    for (int rep = 0; rep < 2; rep++) {
        const int i = tid + rep * 512;
        const float2 v = psi[i];
        #pragma unroll
        for (int p = 0; p < 2; p++) {
            const float val = p ? v.y : v.x;
            const __nv_bfloat16 hi = __float2bfloat16(val);
            const float hif = __bfloat162float(hi);
            const int n = 2 * i + p;
            const int tile = n >> 3;
            // bf16 hi fragment
            const int idx16 = ((tile * 64 + (chunk >> 1) * 32 + (n & 7) * 4 + lq) * 4
                               + (chunk & 1) * 2 + s16) * 2 + h;
            WPH[idx16] = __bfloat16_as_ushort(hi);
            // s8 fragments
            const signed char w8  = to_s8(val * 127.0f);
            const signed char wl8 = to_s8((val - hif) * 32768.0f);
            const int lane = (n & 7) * 4 + lane4;
            const size_t ah = ((((size_t)tile * 64 + (size_t)(jh >> 1) * 32 + lane) * 4)
                               + (jh & 1) * 2 + breg) * 4 + (c & 3);
            const size_t al = ((((size_t)tile * 64 + (size_t)(jl >> 1) * 32 + lane) * 4)
                               + (jl & 1) * 2 + breg) * 4 + (c & 3);
            WQ8[ah] = w8;
            WQ8[al] = wl8;
        }
    }
    // zero the 8-tile padding regions
    if (c == 0) {
        if (tid < 256)
            reinterpret_cast<uint4*>(WPH + 131072)[tid] = make_uint4(0,0,0,0);
        reinterpret_cast<uint4*>(WQ8 + 256*64*16)[tid] = make_uint4(0,0,0,0);
    }
}

// ---------------------------------------------------------------------------
// MMA helpers
// ---------------------------------------------------------------------------
__device__ __forceinline__ void mma16816(float* c,
    const uint32_t* a, uint32_t b0, uint32_t b1)
{
    asm volatile(
        "mma.sync.aligned.m16n8k16.row.col.f32.bf16.bf16.f32 "
        "{%0,%1,%2,%3}, {%4,%5,%6,%7}, {%8,%9}, {%0,%1,%2,%3};"
        : "+f"(c[0]), "+f"(c[1]), "+f"(c[2]), "+f"(c[3])
        : "r"(a[0]), "r"(a[1]), "r"(a[2]), "r"(a[3]), "r"(b0), "r"(b1));
}

__device__ __forceinline__ void mma_s8(int* c,
    const uint32_t* a, uint32_t b0, uint32_t b1)
{
    asm volatile(
        "mma.sync.aligned.m16n8k32.row.col.s32.s8.s8.s32 "
        "{%0,%1,%2,%3}, {%4,%5,%6,%7}, {%8,%9}, {%0,%1,%2,%3};"
        : "+r"(c[0]), "+r"(c[1]), "+r"(c[2]), "+r"(c[3])
        : "r"(a[0]), "r"(a[1]), "r"(a[2]), "r"(a[3]), "r"(b0), "r"(b1));
}

// ---------------------------------------------------------------------------
// Main kernel: 16 tokens/CTA, 8 warps; warp w owns tiles w + 8t (t=0..31).
// grid = 1024, 2 CTAs/SM. Per tile: 4 bf16 k16 MMAs (hi*hi, exact) + 4 s8 k32
// IMMAs (merged correction y_lo*w + y_hi*w_lo, scale 127*2^15, exact s32
// accumulation). Depth-1 register prefetch (the proven R5 loop shape).
// ---------------------------------------------------------------------------
__global__ void __launch_bounds__(256, 2) qsa_main(const float* __restrict__ x,
                                                   float* __restrict__ out)
{
    __shared__ float Y[16][64];
    __shared__ float Q[16][132];
    const int tid  = threadIdx.x;
    const int w    = tid >> 5;
    const int lane = tid & 31;
    const int m0   = blockIdx.x * 16;

    // --- load + L2-normalize 16 tokens ---
    {
        const int tk = tid >> 4;
        const int pp = tid & 15;
        const float4 f = reinterpret_cast<const float4*>(
            x + (size_t)(m0 + tk) * HID)[pp];
        float ssq = f.x*f.x + f.y*f.y + f.z*f.z + f.w*f.w;
        ssq += __shfl_xor_sync(0xffffffffu, ssq, 1);
        ssq += __shfl_xor_sync(0xffffffffu, ssq, 2);
        ssq += __shfl_xor_sync(0xffffffffu, ssq, 4);
        ssq += __shfl_xor_sync(0xffffffffu, ssq, 8);
        const float rn = rsqrtf(ssq);
        Y[tk][pp*4 + 0] = f.x * rn;
        Y[tk][pp*4 + 1] = f.y * rn;
        Y[tk][pp*4 + 2] = f.z * rn;
        Y[tk][pp*4 + 3] = f.w * rn;
    }
    __syncthreads();

    // --- bf16 A fragments (hi only): 4 k-chunks x 4 regs ---
    uint32_t Ah[4][4];
    {
        const int r0 = lane >> 2;
        const int q2 = (lane & 3) * 2;
        #pragma unroll
        for (int ch = 0; ch < 4; ch++)
            #pragma unroll
            for (int rg = 0; rg < 4; rg++) {
                const int row = r0 + 8*(rg & 1);
                const int k = ch*16 + q2 + 8*(rg >> 1);
                const __nv_bfloat16 h0 = __float2bfloat16(Y[row][k]);
                const __nv_bfloat16 h1 = __float2bfloat16(Y[row][k+1]);
                Ah[ch][rg] = ((uint32_t)__bfloat16_as_ushort(h1) << 16)
                           |  __bfloat16_as_ushort(h0);
            }
    }

    // --- s8 A fragments: concat(y_lo*2^15 | y_hi*127), 4 MMAs x 4 regs
    //     (fragment geometry identical to R14's, numerically validated) ---
    uint32_t As8[4][4];
    {
        const int r0 = lane >> 2;
        #pragma unroll
        for (int j = 0; j < 4; j++)
            #pragma unroll
            for (int ri = 0; ri < 4; ri++) {
                const int row = r0 + 8*(ri & 1);
                const int kbase = 32*j + 16*(ri >> 1) + (lane & 3)*4;
                uint32_t pk = 0;
                #pragma unroll
                for (int b = 0; b < 4; b++) {
                    const int kk = kbase + b;
                    float val;
                    if (kk < 64) {
                        const float yv = Y[row][kk];
                        const float yh = __bfloat162float(__float2bfloat16(yv));
                        val = (yv - yh) * 32768.0f;
                    } else {
                        val = __bfloat162float(__float2bfloat16(Y[row][kk - 64])) * 127.0f;
                    }
                    pk |= (uint32_t)(unsigned char)to_s8(val) << (8*b);
                }
                As8[j][ri] = pk;
            }
    }

    // --- main loop: 32 tiles, 8 MMAs each (4 bf16 + 4 s8), depth-1 prefetch ---
    float q[2][4];
    #pragma unroll
    for (int r = 0; r < 2; r++)
        #pragma unroll
        for (int s = 0; s < 4; s++) q[r][s] = 0.f;

    const uint4* pH = reinterpret_cast<const uint4*>(WPH) + w*64 + lane;
    const uint4* pQ = reinterpret_cast<const uint4*>(WQ8) + w*64 + lane;

    uint4 bh0 = pH[0], bh1 = pH[32];
    uint4 q0  = pQ[0], q1  = pQ[32];

    const float invs = 1.0f / (127.0f * 32768.0f);

    #pragma unroll 4
    for (int t = 0; t < 32; t++) {
        pH += 512; pQ += 512;                      // tile += 8 (padded: safe at t=31)
        const uint4 nh0 = pH[0], nh1 = pH[32];
        const uint4 nq0 = pQ[0], nq1 = pQ[32];

        float h0[4] = {0.f,0.f,0.f,0.f};
        float h1[4] = {0.f,0.f,0.f,0.f};
        int   i0[4] = {0,0,0,0};
        int   i1[4] = {0,0,0,0};
        // four independent chains of 2 across two pipes
        mma16816(h0, Ah[0],  bh0.x, bh0.y);
        mma16816(h1, Ah[1],  bh0.z, bh0.w);
        mma_s8 (i0, As8[0], q0.x,  q0.y);
        mma_s8 (i1, As8[1], q0.z,  q0.w);
        mma16816(h0, Ah[2],  bh1.x, bh1.y);
        mma16816(h1, Ah[3],  bh1.z, bh1.w);
        mma_s8 (i0, As8[2], q1.x,  q1.y);
        mma_s8 (i1, As8[3], q1.z,  q1.w);

        const int s = t & 3;
        const float e0 = fmaf(__int2float_rn(i0[0] + i1[0]), invs, h0[0] + h1[0]);
        const float e1 = fmaf(__int2float_rn(i0[1] + i1[1]), invs, h0[1] + h1[1]);
        const float e2 = fmaf(__int2float_rn(i0[2] + i1[2]), invs, h0[2] + h1[2]);
        const float e3 = fmaf(__int2float_rn(i0[3] + i1[3]), invs, h0[3] + h1[3]);
        q[0][s] = fmaf(e0, e0, fmaf(e1, e1, q[0][s]));
        q[1][s] = fmaf(e2, e2, fmaf(e3, e3, q[1][s]));

        bh0 = nh0; bh1 = nh1; q0 = nq0; q1 = nq1;
    }

    // --- scatter q into Q[token][j], j = 4w + 32s + (lane&3); disjoint per warp ---
    #pragma unroll
    for (int r = 0; r < 2; r++)
        #pragma unroll
        for (int s = 0; s < 4; s++) {
            const int tok = r*8 + (lane >> 2);
            const int j = 4*w + 32*s + (lane & 3);
            Q[tok][j] = q[r][s];
        }
    __syncthreads();

    // --- 128-pt WHT per token (warp w: tokens 2w, 2w+1), store out[k] = F[k+1] ---
    #pragma unroll
    for (int tt = 0; tt < 2; tt++) {
        const int tok = w*2 + tt;
        float f0 = Q[tok][lane];
        float f1 = Q[tok][lane + 32];
        float f2 = Q[tok][lane + 64];
        float f3 = Q[tok][lane + 96];
        float a0 = f0 + f1, a1 = f0 - f1, a2 = f2 + f3, a3 = f2 - f3;
        f0 = a0 + a2; f2 = a0 - a2; f1 = a1 + a3;
        #pragma unroll
        for (int e = 1; e <= 16; e <<= 1) {
            float p;
            p = __shfl_xor_sync(0xffffffffu, f0, e); f0 = (lane & e) ? (p - f0) : (f0 + p);
            p = __shfl_xor_sync(0xffffffffu, f1, e); f1 = (lane & e) ? (p - f1) : (f1 + p);
            p = __shfl_xor_sync(0xffffffffu, f2, e); f2 = (lane & e) ? (p - f2) : (f2 + p);
        }
        float* orow = out + (size_t)(m0 + tok) * HID;
        if (lane >= 1) orow[lane - 1] = f0;     // F[1..31]  -> k 0..30
        orow[lane + 31] = f1;                   // F[32..63] -> k 31..62
        if (lane == 0) orow[63] = f2;           // F[64]     -> k 63
    }
}

extern "C" void kernel_launch(void* const* d_in, const int* in_sizes, int n_in,
                              void* d_out, int out_size)
{
    const float* x   = (const float*)d_in[0];
    const float* rx0 = (const float*)d_in[1];
    const float* ry0 = (const float*)d_in[2];
    const float* ry1 = (const float*)d_in[3];
    float* out = (float*)d_out;

    const int M = in_sizes[0] / HID;   // 16384 tokens

    qsa_circuit<<<HID, 512>>>(rx0, ry0, ry1);   // W -> bf16-hi + s8 fragments
    qsa_main<<<M / 16, 256>>>(x, out);          // 8-MMA/tile GEMM + fold + WHT
}

// round 16
// speedup vs baseline: 1.8994x; 1.8994x over previous
#include <cuda_runtime.h>
#include <cuda_fp16.h>
#include <cstdint>

#define NW 10
#define DIM 1024
#define HID 64

// W stored as f16 in the HMMA k16 B-fragment layout (geometry validated
// R3-R15), +4096 shorts padding for the depth-1 prefetch overrun.
// WFH = f16(w) ; WFL = f16((w - f16(w)) * 256).
__device__ __align__(16) unsigned short WFH[131072 + 4096];
__device__ __align__(16) unsigned short WFL[131072 + 4096];

// ---------------------------------------------------------------------------
// Circuit kernel (R11 reductions): fused RXRY, CNOT ring as one gather,
// RY1 dropped on qubits 0-2 (summed-out bits; output invariant).
// ---------------------------------------------------------------------------
__device__ __forceinline__ void gate1q(float2* psi, int tid, int bit,
    float g00x, float g00y, float g01x, float g01y,
    float g10x, float g10y, float g11x, float g11y)
{
    const int lowmask = bit - 1;
    const int i0 = ((tid & ~lowmask) << 1) | (tid & lowmask);
    const int i1 = i0 | bit;
    const float2 a = psi[i0], b = psi[i1];
    float2 n0, n1;
    n0.x = g00x*a.x - g00y*a.y + g01x*b.x - g01y*b.y;
    n0.y = g00x*a.y + g00y*a.x + g01x*b.y + g01y*b.x;
    n1.x = g10x*a.x - g10y*a.y + g11x*b.x - g11y*b.y;
    n1.y = g10x*a.y + g10y*a.x + g11x*b.y + g11y*b.x;
    psi[i0] = n0; psi[i1] = n1;
}

__global__ void qsa_circuit(const float* __restrict__ rx0,
                            const float* __restrict__ ry0,
                            const float* __restrict__ ry1)
{
    __shared__ float2 psi[DIM];
    const int tid = threadIdx.x;   // 512
    const int c = blockIdx.x;      // 0..63

    psi[tid]       = make_float2(0.f, 0.f);
    psi[tid + 512] = make_float2(0.f, 0.f);
    __syncthreads();
    if (tid == 0) psi[c] = make_float2(1.f, 0.f);
    __syncthreads();

    for (int j = 0; j < NW; j++) {
        const int bit = 1 << (NW - 1 - j);
        float s1, c1, s2, c2;
        sincosf(0.5f * rx0[j], &s1, &c1);
        sincosf(0.5f * ry0[j], &s2, &c2);
        gate1q(psi, tid, bit,
               c2*c1,  s2*s1,  -s2*c1, -c2*s1,
               s2*c1, -c2*s1,   c2*c1, -s2*s1);
        __syncthreads();
    }
    {   // CNOT ring: one permutation gather
        float2 v[2];
        #pragma unroll
        for (int rep = 0; rep < 2; rep++) {
            int src = tid + rep * 512;
            #pragma unroll
            for (int j = NW - 1; j >= 0; j--) {
                const int cbit = 1 << (NW - 1 - j);
                const int tbit = 1 << (NW - 1 - ((j + 1) % NW));
                if (src & cbit) src ^= tbit;
            }
            v[rep] = psi[src];
        }
        __syncthreads();
        psi[tid]       = v[0];
        psi[tid + 512] = v[1];
        __syncthreads();
    }
    for (int j = 3; j < NW; j++) {
        const int bit = 1 << (NW - 1 - j);
        float s, cc;
        sincosf(0.5f * ry1[j], &s, &cc);
        gate1q(psi, tid, bit, cc, 0.f, -s, 0.f, s, 0.f, cc, 0.f);
        __syncthreads();
    }

    // scatter column c into f16 hi/lo B fragments
    const int chunk = c >> 4;
    const int s16 = (c >> 3) & 1;
    const int lq  = (c & 7) >> 1;
    const int h   = c & 1;
    #pragma unroll
    for (int rep = 0; rep < 2; rep++) {
        const int i = tid + rep * 512;
        const float2 v = psi[i];
        #pragma unroll
        for (int p = 0; p < 2; p++) {
            const float val = p ? v.y : v.x;
            const __half w1 = __float2half(val);
            const __half w2 = __float2half((val - __half2float(w1)) * 256.0f);
            const int n = 2 * i + p;
            const int tile = n >> 3;
            const int idx = ((tile * 64 + (chunk >> 1) * 32 + (n & 7) * 4 + lq) * 4
                             + (chunk & 1) * 2 + s16) * 2 + h;
            WFH[idx] = __half_as_ushort(w1);
            WFL[idx] = __half_as_ushort(w2);
        }
    }
    // zero the padding tiles (256 uint4 per array)
    if (c == 0 && tid < 256) {
        reinterpret_cast<uint4*>(WFH + 131072)[tid] = make_uint4(0,0,0,0);
        reinterpret_cast<uint4*>(WFL + 131072)[tid] = make_uint4(0,0,0,0);
    }
}

// ---------------------------------------------------------------------------
// MMA helpers: f16 inputs; f32 accum for the main term, f16 accum for the
// corrections (testing the f16-acc double-rate hypothesis).
// ---------------------------------------------------------------------------
__device__ __forceinline__ void mma_f32acc(float* c,
    const uint32_t* a, uint32_t b0, uint32_t b1)
{
    asm volatile(
        "mma.sync.aligned.m16n8k16.row.col.f32.f16.f16.f32 "
        "{%0,%1,%2,%3}, {%4,%5,%6,%7}, {%8,%9}, {%0,%1,%2,%3};"
        : "+f"(c[0]), "+f"(c[1]), "+f"(c[2]), "+f"(c[3])
        : "r"(a[0]), "r"(a[1]), "r"(a[2]), "r"(a[3]), "r"(b0), "r"(b1));
}

__device__ __forceinline__ void mma_f16acc(uint32_t* c,
    const uint32_t* a, uint32_t b0, uint32_t b1)
{
    asm volatile(
        "mma.sync.aligned.m16n8k16.row.col.f16.f16.f16.f16 "
        "{%0,%1}, {%2,%3,%4,%5}, {%6,%7}, {%0,%1};"
        : "+r"(c[0]), "+r"(c[1])
        : "r"(a[0]), "r"(a[1]), "r"(a[2]), "r"(a[3]), "r"(b0), "r"(b1));
}

// ---------------------------------------------------------------------------
// Main kernel: 16 tokens/CTA, 8 warps; warp w owns tiles w + 8t (t=0..31).
// grid = 1024, 2 CTAs/SM, depth-1 register prefetch (the proven R5 shape).
// Per tile: 4 f32-acc MMAs (y1*w1) + 8 f16-acc MMAs (y2*w1, y1*w2, both *256).
// ---------------------------------------------------------------------------
__global__ void __launch_bounds__(256, 2) qsa_main(const float* __restrict__ x,
                                                   float* __restrict__ out)
{
    __shared__ float Y[16][64];
    __shared__ float Q[16][132];
    const int tid  = threadIdx.x;
    const int w    = tid >> 5;
    const int lane = tid & 31;
    const int m0   = blockIdx.x * 16;

    // --- load + L2-normalize 16 tokens ---
    {
        const int tk = tid >> 4;
        const int pp = tid & 15;
        const float4 f = reinterpret_cast<const float4*>(
            x + (size_t)(m0 + tk) * HID)[pp];
        float ssq = f.x*f.x + f.y*f.y + f.z*f.z + f.w*f.w;
        ssq += __shfl_xor_sync(0xffffffffu, ssq, 1);
        ssq += __shfl_xor_sync(0xffffffffu, ssq, 2);
        ssq += __shfl_xor_sync(0xffffffffu, ssq, 4);
        ssq += __shfl_xor_sync(0xffffffffu, ssq, 8);
        const float rn = rsqrtf(ssq);
        Y[tk][pp*4 + 0] = f.x * rn;
        Y[tk][pp*4 + 1] = f.y * rn;
        Y[tk][pp*4 + 2] = f.z * rn;
        Y[tk][pp*4 + 3] = f.w * rn;
    }
    __syncthreads();

    // --- A fragments: 4 k-chunks x 4 regs, f16 hi (y1) and f16 lo (y2*256) ---
    uint32_t A1[4][4], A2[4][4];
    {
        const int r0 = lane >> 2;
        const int q2 = (lane & 3) * 2;
        #pragma unroll
        for (int ch = 0; ch < 4; ch++)
            #pragma unroll
            for (int rg = 0; rg < 4; rg++) {
                const int row = r0 + 8*(rg & 1);
                const int k = ch*16 + q2 + 8*(rg >> 1);
                const float y0 = Y[row][k], y1 = Y[row][k+1];
                const __half h0 = __float2half(y0);
                const __half h1 = __float2half(y1);
                const __half l0 = __float2half((y0 - __half2float(h0)) * 256.0f);
                const __half l1 = __float2half((y1 - __half2float(h1)) * 256.0f);
                A1[ch][rg] = ((uint32_t)__half_as_ushort(h1) << 16)
                           |  __half_as_ushort(h0);
                A2[ch][rg] = ((uint32_t)__half_as_ushort(l1) << 16)
                           |  __half_as_ushort(l0);
            }
    }

    // --- main loop: 32 tiles, 3 chains of 4 (1 f32-acc + 2 f16-acc) ---
    float q[2][4];
    #pragma unroll
    for (int r = 0; r < 2; r++)
        #pragma unroll
        for (int s = 0; s < 4; s++) q[r][s] = 0.f;

    const uint4* pH = reinterpret_cast<const uint4*>(WFH) + w*64 + lane;
    const uint4* pL = reinterpret_cast<const uint4*>(WFL) + w*64 + lane;

    uint4 bh0 = pH[0], bh1 = pH[32];
    uint4 bl0 = pL[0], bl1 = pL[32];

    const float inv256 = 1.0f / 256.0f;

    #pragma unroll 4
    for (int t = 0; t < 32; t++) {
        pH += 512; pL += 512;                       // tile += 8 (padded: safe at t=31)
        const uint4 nh0 = pH[0], nh1 = pH[32];
        const uint4 nl0 = pL[0], nl1 = pL[32];

        float    hh[4] = {0.f,0.f,0.f,0.f};
        uint32_t lh[2] = {0u,0u};                   // f16x2 accum (c0,c1 | c2,c3)
        uint32_t hl[2] = {0u,0u};
        mma_f32acc(hh, A1[0], bh0.x, bh0.y);
        mma_f16acc(lh, A2[0], bh0.x, bh0.y);
        mma_f16acc(hl, A1[0], bl0.x, bl0.y);
        mma_f32acc(hh, A1[1], bh0.z, bh0.w);
        mma_f16acc(lh, A2[1], bh0.z, bh0.w);
        mma_f16acc(hl, A1[1], bl0.z, bl0.w);
        mma_f32acc(hh, A1[2], bh1.x, bh1.y);
        mma_f16acc(lh, A2[2], bh1.x, bh1.y);
        mma_f16acc(hl, A1[2], bl1.x, bl1.y);
        mma_f32acc(hh, A1[3], bh1.z, bh1.w);
        mma_f16acc(lh, A2[3], bh1.z, bh1.w);
        mma_f16acc(hl, A1[3], bl1.z, bl1.w);

        // corrections: (lh + hl) * 2^-8, added to the exact f32 main term
        const __half2 s0 = __hadd2(*reinterpret_cast<__half2*>(&lh[0]),
                                   *reinterpret_cast<__half2*>(&hl[0]));
        const __half2 s1 = __hadd2(*reinterpret_cast<__half2*>(&lh[1]),
                                   *reinterpret_cast<__half2*>(&hl[1]));
        const float2 f01 = __half22float2(s0);
        const float2 f23 = __half22float2(s1);
        const float c0 = fmaf(f01.x, inv256, hh[0]);
        const float c1 = fmaf(f01.y, inv256, hh[1]);
        const float c2 = fmaf(f23.x, inv256, hh[2]);
        const float c3 = fmaf(f23.y, inv256, hh[3]);

        const int s = t & 3;
        q[0][s] = fmaf(c0, c0, fmaf(c1, c1, q[0][s]));
        q[1][s] = fmaf(c2, c2, fmaf(c3, c3, q[1][s]));

        bh0 = nh0; bh1 = nh1; bl0 = nl0; bl1 = nl1;
    }

    // --- scatter q into Q[token][j], j = 4w + 32s + (lane&3); disjoint per warp ---
    #pragma unroll
    for (int r = 0; r < 2; r++)
        #pragma unroll
        for (int s = 0; s < 4; s++) {
            const int tok = r*8 + (lane >> 2);
            const int j = 4*w + 32*s + (lane & 3);
            Q[tok][j] = q[r][s];
        }
    __syncthreads();

    // --- 128-pt WHT per token (warp w: tokens 2w, 2w+1), store out[k] = F[k+1] ---
    #pragma unroll
    for (int tt = 0; tt < 2; tt++) {
        const int tok = w*2 + tt;
        float f0 = Q[tok][lane];
        float f1 = Q[tok][lane + 32];
        float f2 = Q[tok][lane + 64];
        float f3 = Q[tok][lane + 96];
        float a0 = f0 + f1, a1 = f0 - f1, a2 = f2 + f3, a3 = f2 - f3;
        f0 = a0 + a2; f2 = a0 - a2; f1 = a1 + a3;
        #pragma unroll
        for (int e = 1; e <= 16; e <<= 1) {
            float p;
            p = __shfl_xor_sync(0xffffffffu, f0, e); f0 = (lane & e) ? (p - f0) : (f0 + p);
            p = __shfl_xor_sync(0xffffffffu, f1, e); f1 = (lane & e) ? (p - f1) : (f1 + p);
            p = __shfl_xor_sync(0xffffffffu, f2, e); f2 = (lane & e) ? (p - f2) : (f2 + p);
        }
        float* orow = out + (size_t)(m0 + tok) * HID;
        if (lane >= 1) orow[lane - 1] = f0;     // F[1..31]  -> k 0..30
        orow[lane + 31] = f1;                   // F[32..63] -> k 31..62
        if (lane == 0) orow[63] = f2;           // F[64]     -> k 63
    }
}

extern "C" void kernel_launch(void* const* d_in, const int* in_sizes, int n_in,
                              void* d_out, int out_size)
{
    const float* x   = (const float*)d_in[0];
    const float* rx0 = (const float*)d_in[1];
    const float* ry0 = (const float*)d_in[2];
    const float* ry1 = (const float*)d_in[3];
    float* out = (float*)d_out;

    const int M = in_sizes[0] / HID;   // 16384 tokens

    qsa_circuit<<<HID, 512>>>(rx0, ry0, ry1);   // W -> f16 hi/lo B fragments
    qsa_main<<<M / 16, 256>>>(x, out);          // mixed-acc HMMA GEMM + fold + WHT
}